// round 9
// baseline (speedup 1.0000x reference)
#include <cuda_runtime.h>

// GCN_75050258530542 — round 9: k_out 2 nodes/warp-iter (6 batched LDG),
// k_prep 2 nodes/thread (8 batched LDG). Scatter/degree unchanged (at floor).
// out[n,:] = rsqrt(deg_in[n]) * (sum_{e:dst=n} x[src,15:25]*rsqrt(deg_out[src])) @ (W1@W2)
//            + (b1@W2 + b2)

constexpr int NMAX = 100000;
constexpr int FP   = 16;   // 64B rows, 128B-aligned: 4-lane group hits 1 line

__device__ int g_deg_out[NMAX];
__device__ __align__(128) float g_xsn[NMAX * FP];   // slots 0-9 = x[:,15:25]*norm_s; pad 0
__device__ __align__(128) float g_agg[NMAX * FP];   // slots 0-9 sums, slot 10 = deg_in
__device__ float g_Weff[640];                       // W1@W2 (10 x 64)
__device__ float g_beff[64];                        // b1@W2 + b2

// ---------------------------------------------------------------- degrees + weff (last block)
__global__ void k_deg_weff(const int* __restrict__ src, int E,
                           const float* __restrict__ W1, const float* __restrict__ b1,
                           const float* __restrict__ W2, const float* __restrict__ b2) {
    int nb = gridDim.x - 1;
    if ((int)blockIdx.x == nb) {
        for (int idx = threadIdx.x; idx < 704; idx += blockDim.x) {
            if (idx < 640) {
                int i = idx >> 6, j = idx & 63;
                float s = 0.f;
#pragma unroll 8
                for (int k = 0; k < 128; k++) s += W1[i * 128 + k] * W2[k * 64 + j];
                g_Weff[idx] = s;
            } else {
                int j = idx - 640;
                float s = b2[j];
#pragma unroll 8
                for (int k = 0; k < 128; k++) s += b1[k] * W2[k * 64 + j];
                g_beff[j] = s;
            }
        }
        return;
    }
    int n8 = E >> 3;
    int stride = nb * blockDim.x;
    for (int t = blockIdx.x * blockDim.x + threadIdx.x; t < n8; t += stride) {
        int4 s0 = reinterpret_cast<const int4*>(src)[2 * t];
        int4 s1 = reinterpret_cast<const int4*>(src)[2 * t + 1];
        atomicAdd(&g_deg_out[s0.x], 1);
        atomicAdd(&g_deg_out[s0.y], 1);
        atomicAdd(&g_deg_out[s0.z], 1);
        atomicAdd(&g_deg_out[s0.w], 1);
        atomicAdd(&g_deg_out[s1.x], 1);
        atomicAdd(&g_deg_out[s1.y], 1);
        atomicAdd(&g_deg_out[s1.z], 1);
        atomicAdd(&g_deg_out[s1.w], 1);
    }
    if (blockIdx.x == 0 && threadIdx.x == 0) {
        for (int e = (n8 << 3); e < E; e++) atomicAdd(&g_deg_out[src[e]], 1);
    }
}

// ---------------------------------------------------------------- prep: 2 nodes/thread, batched loads
__global__ void k_prep(const float* __restrict__ x, int N) {
    int t = blockIdx.x * blockDim.x + threadIdx.x;
    int i0 = 2 * t;
    if (i0 >= N) return;
    int i1 = i0 + 1;
    bool two = (i1 < N);

    int d0 = g_deg_out[i0];
    int d1 = two ? g_deg_out[i1] : 1;

    const float* ba = x + (size_t)i0 * 40;
    const float* bb = x + (size_t)i1 * 40;
    float4 A0 = *reinterpret_cast<const float4*>(ba + 12);
    float4 A1 = *reinterpret_cast<const float4*>(ba + 16);
    float4 A2 = *reinterpret_cast<const float4*>(ba + 20);
    float4 A3 = *reinterpret_cast<const float4*>(ba + 24);
    float4 B0, B1, B2, B3;
    if (two) {
        B0 = *reinterpret_cast<const float4*>(bb + 12);
        B1 = *reinterpret_cast<const float4*>(bb + 16);
        B2 = *reinterpret_cast<const float4*>(bb + 20);
        B3 = *reinterpret_cast<const float4*>(bb + 24);
    }
    float ns0 = rsqrtf(d0 > 0 ? (float)d0 : 1.f);
    float* o0 = g_xsn + (size_t)i0 * FP;
    *reinterpret_cast<float4*>(o0)     = make_float4(A0.w * ns0, A1.x * ns0, A1.y * ns0, A1.z * ns0);
    *reinterpret_cast<float4*>(o0 + 4) = make_float4(A1.w * ns0, A2.x * ns0, A2.y * ns0, A2.z * ns0);
    *reinterpret_cast<float4*>(o0 + 8) = make_float4(A2.w * ns0, A3.x * ns0, 0.f, 0.f);
    if (two) {
        float ns1 = rsqrtf(d1 > 0 ? (float)d1 : 1.f);
        float* o1 = g_xsn + (size_t)i1 * FP;
        *reinterpret_cast<float4*>(o1)     = make_float4(B0.w * ns1, B1.x * ns1, B1.y * ns1, B1.z * ns1);
        *reinterpret_cast<float4*>(o1 + 4) = make_float4(B1.w * ns1, B2.x * ns1, B2.y * ns1, B2.z * ns1);
        *reinterpret_cast<float4*>(o1 + 8) = make_float4(B2.w * ns1, B3.x * ns1, 0.f, 0.f);
    }
}

// ---------------------------------------------------------------- vector RED
__device__ __forceinline__ void red4(float* p, float a, float b, float c, float d) {
    asm volatile("red.global.add.v4.f32 [%0], {%1,%2,%3,%4};"
                 :: "l"(p), "f"(a), "f"(b), "f"(c), "f"(d) : "memory");
}

// ---------------------------------------------------------------- scatter: 4 lanes/edge, 8 edges/group
__global__ void __launch_bounds__(256) k_scatter(const int* __restrict__ src,
                                                 const int* __restrict__ dst, int E) {
    int tid = blockIdx.x * blockDim.x + threadIdx.x;
    int g = tid >> 2;          // edge group (8 edges)
    int q = tid & 3;           // quarter within feature row
    long base = (long)g * 8;
    if (base >= E) return;

    unsigned am = 0xffffffffu;
    int full = (base + 8 <= (long)E);

    int dd[8];
    float4 v[8];
    if (full) {
        int s2a = __ldg(src + base + 2 * q);
        int s2b = __ldg(src + base + 2 * q + 1);
        int d2a = __ldg(dst + base + 2 * q);
        int d2b = __ldg(dst + base + 2 * q + 1);
        int lq = (tid & 31) & ~3;
#pragma unroll
        for (int j = 0; j < 8; j++) {
            int owner = lq + (j >> 1);
            int sj = __shfl_sync(am, (j & 1) ? s2b : s2a, owner);
            dd[j]  = __shfl_sync(am, (j & 1) ? d2b : d2a, owner);
            if (q < 3) v[j] = *reinterpret_cast<const float4*>(g_xsn + (size_t)sj * FP + q * 4);
        }
#pragma unroll
        for (int j = 0; j < 8; j++) {
            if (q < 3) {
                float4 p = v[j];
                if (q == 2) { p.z = 1.0f; p.w = 0.0f; }   // slot 10 += 1 (deg_in)
                red4(g_agg + (size_t)dd[j] * FP + q * 4, p.x, p.y, p.z, p.w);
            }
        }
    } else {
        int cnt = (int)(E - base);
        for (int j = 0; j < cnt; j++) {
            int sj = __ldg(src + base + j);
            int dj = __ldg(dst + base + j);
            if (q < 3) {
                float4 p = *reinterpret_cast<const float4*>(g_xsn + (size_t)sj * FP + q * 4);
                if (q == 2) { p.z = 1.0f; p.w = 0.0f; }
                red4(g_agg + (size_t)dj * FP + q * 4, p.x, p.y, p.z, p.w);
            }
        }
    }
}

// ---------------------------------------------------------------- warp-per-node output, 2 nodes/iter
__global__ void __launch_bounds__(256) k_out(float* __restrict__ out, int N) {
    __shared__ float sW[640];
    __shared__ float sb[64];
    int t = threadIdx.x;
    for (int k = t; k < 640; k += 256) sW[k] = g_Weff[k];
    if (t < 64) sb[t] = g_beff[t];
    __syncthreads();

    int lane = t & 31;
    int warp = t >> 5;
    float w0[10], w1[10];
#pragma unroll
    for (int k = 0; k < 10; k++) {
        w0[k] = sW[k * 64 + lane];
        w1[k] = sW[k * 64 + 32 + lane];
    }
    float b0 = sb[lane];
    float b1 = sb[lane + 32];

    int step = gridDim.x * 16;                 // 16 nodes per block-iter (8 warps x 2)
    for (int nb = blockIdx.x * 16 + warp * 2; nb < N; nb += step) {
        // nb is even; N even => nb+1 < N always valid when nb < N
        const float4* arA = reinterpret_cast<const float4*>(g_agg + (size_t)nb * FP);
        const float4* arB = reinterpret_cast<const float4*>(g_agg + (size_t)(nb + 1) * FP);
        float4 a0 = arA[0], a1 = arA[1], a2 = arA[2];
        float4 c0 = arB[0], c1 = arB[1], c2 = arB[2];

        float ndA = rsqrtf(a2.z > 0.f ? a2.z : 1.f);
        float ndB = rsqrtf(c2.z > 0.f ? c2.z : 1.f);

        float sA0 = a0.x * w0[0] + a0.y * w0[1] + a0.z * w0[2] + a0.w * w0[3]
                  + a1.x * w0[4] + a1.y * w0[5] + a1.z * w0[6] + a1.w * w0[7]
                  + a2.x * w0[8] + a2.y * w0[9];
        float sA1 = a0.x * w1[0] + a0.y * w1[1] + a0.z * w1[2] + a0.w * w1[3]
                  + a1.x * w1[4] + a1.y * w1[5] + a1.z * w1[6] + a1.w * w1[7]
                  + a2.x * w1[8] + a2.y * w1[9];
        float sB0 = c0.x * w0[0] + c0.y * w0[1] + c0.z * w0[2] + c0.w * w0[3]
                  + c1.x * w0[4] + c1.y * w0[5] + c1.z * w0[6] + c1.w * w0[7]
                  + c2.x * w0[8] + c2.y * w0[9];
        float sB1 = c0.x * w1[0] + c0.y * w1[1] + c0.z * w1[2] + c0.w * w1[3]
                  + c1.x * w1[4] + c1.y * w1[5] + c1.z * w1[6] + c1.w * w1[7]
                  + c2.x * w1[8] + c2.y * w1[9];

        float* oA = out + (size_t)nb * 64;
        float* oB = oA + 64;
        oA[lane]      = b0 + ndA * sA0;
        oA[lane + 32] = b1 + ndA * sA1;
        oB[lane]      = b0 + ndB * sB0;
        oB[lane + 32] = b1 + ndB * sB1;
    }
}

// ---------------------------------------------------------------- launch
extern "C" void kernel_launch(void* const* d_in, const int* in_sizes, int n_in,
                              void* d_out, int out_size) {
    const float* x   = (const float*)d_in[0];
    const int*   src = (const int*)d_in[1];
    const int*   dst = (const int*)d_in[2];
    const float* W1  = (const float*)d_in[3];
    const float* b1  = (const float*)d_in[4];
    const float* W2  = (const float*)d_in[5];
    const float* b2  = (const float*)d_in[6];
    float* out = (float*)d_out;

    int N = in_sizes[0] / 40;
    int E = in_sizes[1];

    void* p_agg = nullptr;
    void* p_deg = nullptr;
    cudaGetSymbolAddress(&p_agg, g_agg);
    cudaGetSymbolAddress(&p_deg, g_deg_out);
    cudaMemsetAsync(p_agg, 0, (size_t)N * FP * sizeof(float));
    cudaMemsetAsync(p_deg, 0, (size_t)N * sizeof(int));

    int n8 = E >> 3;
    int db = (n8 > 0 ? (n8 + 255) / 256 : 1) + 1;          // +1 block for weff
    k_deg_weff<<<db, 256>>>(src, E, W1, b1, W2, b2);

    int nt = (N + 1) / 2;                                   // 2 nodes per thread
    k_prep<<<(nt + 255) / 256, 256>>>(x, N);

    long groups = ((long)E + 7) / 8;                        // 4 lanes per group
    long sthreads = groups * 4;
    int sblocks = (int)((sthreads + 255) / 256);
    k_scatter<<<sblocks, 256>>>(src, dst, E);

    k_out<<<1184, 256>>>(out, N);                           // 2 nodes per warp-iter
}

// round 10
// speedup vs baseline: 1.5175x; 1.5175x over previous
#include <cuda_runtime.h>

// GCN_75050258530542 — round 10: R8 base + smem-staged k_out (block-tile bulk
// copy of agg rows into smem, then warp-per-node compute from LDS).
// out[n,:] = rsqrt(deg_in[n]) * (sum_{e:dst=n} x[src,15:25]*rsqrt(deg_out[src])) @ (W1@W2)
//            + (b1@W2 + b2)

constexpr int NMAX = 100000;
constexpr int FP   = 16;   // 64B rows, 128B-aligned: 4-lane group hits 1 line

__device__ int g_deg_out[NMAX];
__device__ __align__(128) float g_xsn[NMAX * FP];   // slots 0-9 = x[:,15:25]*norm_s; pad 0
__device__ __align__(128) float g_agg[NMAX * FP];   // slots 0-9 sums, slot 10 = deg_in
__device__ float g_Weff[640];                       // W1@W2 (10 x 64)
__device__ float g_beff[64];                        // b1@W2 + b2

// ---------------------------------------------------------------- degrees + weff (last block)
__global__ void k_deg_weff(const int* __restrict__ src, int E,
                           const float* __restrict__ W1, const float* __restrict__ b1,
                           const float* __restrict__ W2, const float* __restrict__ b2) {
    int nb = gridDim.x - 1;
    if ((int)blockIdx.x == nb) {
        for (int idx = threadIdx.x; idx < 704; idx += blockDim.x) {
            if (idx < 640) {
                int i = idx >> 6, j = idx & 63;
                float s = 0.f;
#pragma unroll 8
                for (int k = 0; k < 128; k++) s += W1[i * 128 + k] * W2[k * 64 + j];
                g_Weff[idx] = s;
            } else {
                int j = idx - 640;
                float s = b2[j];
#pragma unroll 8
                for (int k = 0; k < 128; k++) s += b1[k] * W2[k * 64 + j];
                g_beff[j] = s;
            }
        }
        return;
    }
    int n8 = E >> 3;
    int stride = nb * blockDim.x;
    for (int t = blockIdx.x * blockDim.x + threadIdx.x; t < n8; t += stride) {
        int4 s0 = reinterpret_cast<const int4*>(src)[2 * t];
        int4 s1 = reinterpret_cast<const int4*>(src)[2 * t + 1];
        atomicAdd(&g_deg_out[s0.x], 1);
        atomicAdd(&g_deg_out[s0.y], 1);
        atomicAdd(&g_deg_out[s0.z], 1);
        atomicAdd(&g_deg_out[s0.w], 1);
        atomicAdd(&g_deg_out[s1.x], 1);
        atomicAdd(&g_deg_out[s1.y], 1);
        atomicAdd(&g_deg_out[s1.z], 1);
        atomicAdd(&g_deg_out[s1.w], 1);
    }
    if (blockIdx.x == 0 && threadIdx.x == 0) {
        for (int e = (n8 << 3); e < E; e++) atomicAdd(&g_deg_out[src[e]], 1);
    }
}

// ---------------------------------------------------------------- prep: xsn = x[:,15:25]*norm_s (R8 version)
__global__ void k_prep(const float* __restrict__ x, int N) {
    int i = blockIdx.x * blockDim.x + threadIdx.x;
    if (i >= N) return;
    int dout = g_deg_out[i];
    float ns = rsqrtf(dout > 0 ? (float)dout : 1.f);
    const float* base = x + (size_t)i * 40;
    float4 L0 = *reinterpret_cast<const float4*>(base + 12);  // cols 12-15
    float4 L1 = *reinterpret_cast<const float4*>(base + 16);  // cols 16-19
    float4 L2 = *reinterpret_cast<const float4*>(base + 20);  // cols 20-23
    float4 L3 = *reinterpret_cast<const float4*>(base + 24);  // cols 24-27
    float* o = g_xsn + i * FP;
    *reinterpret_cast<float4*>(o)     = make_float4(L0.w * ns, L1.x * ns, L1.y * ns, L1.z * ns); // c15-18
    *reinterpret_cast<float4*>(o + 4) = make_float4(L1.w * ns, L2.x * ns, L2.y * ns, L2.z * ns); // c19-22
    *reinterpret_cast<float4*>(o + 8) = make_float4(L2.w * ns, L3.x * ns, 0.f, 0.f);             // c23-24, pad
}

// ---------------------------------------------------------------- vector RED
__device__ __forceinline__ void red4(float* p, float a, float b, float c, float d) {
    asm volatile("red.global.add.v4.f32 [%0], {%1,%2,%3,%4};"
                 :: "l"(p), "f"(a), "f"(b), "f"(c), "f"(d) : "memory");
}

// ---------------------------------------------------------------- scatter: 4 lanes/edge, 8 edges/group
__global__ void __launch_bounds__(256) k_scatter(const int* __restrict__ src,
                                                 const int* __restrict__ dst, int E) {
    int tid = blockIdx.x * blockDim.x + threadIdx.x;
    int g = tid >> 2;          // edge group (8 edges)
    int q = tid & 3;           // quarter within feature row
    long base = (long)g * 8;
    if (base >= E) return;

    unsigned am = 0xffffffffu;
    int full = (base + 8 <= (long)E);

    int dd[8];
    float4 v[8];
    if (full) {
        int s2a = __ldg(src + base + 2 * q);
        int s2b = __ldg(src + base + 2 * q + 1);
        int d2a = __ldg(dst + base + 2 * q);
        int d2b = __ldg(dst + base + 2 * q + 1);
        int lq = (tid & 31) & ~3;
#pragma unroll
        for (int j = 0; j < 8; j++) {
            int owner = lq + (j >> 1);
            int sj = __shfl_sync(am, (j & 1) ? s2b : s2a, owner);
            dd[j]  = __shfl_sync(am, (j & 1) ? d2b : d2a, owner);
            if (q < 3) v[j] = *reinterpret_cast<const float4*>(g_xsn + (size_t)sj * FP + q * 4);
        }
#pragma unroll
        for (int j = 0; j < 8; j++) {
            if (q < 3) {
                float4 p = v[j];
                if (q == 2) { p.z = 1.0f; p.w = 0.0f; }   // slot 10 += 1 (deg_in)
                red4(g_agg + (size_t)dd[j] * FP + q * 4, p.x, p.y, p.z, p.w);
            }
        }
    } else {
        int cnt = (int)(E - base);
        for (int j = 0; j < cnt; j++) {
            int sj = __ldg(src + base + j);
            int dj = __ldg(dst + base + j);
            if (q < 3) {
                float4 p = *reinterpret_cast<const float4*>(g_xsn + (size_t)sj * FP + q * 4);
                if (q == 2) { p.z = 1.0f; p.w = 0.0f; }
                red4(g_agg + (size_t)dj * FP + q * 4, p.x, p.y, p.z, p.w);
            }
        }
    }
}

// ---------------------------------------------------------------- k_out: smem-staged block tile (128 nodes)
__global__ void __launch_bounds__(256) k_out(float* __restrict__ out, int N) {
    __shared__ float sW[640];
    __shared__ float sb[64];
    __shared__ __align__(16) float sAgg[128 * FP];   // 8KB tile
    int t = threadIdx.x;

    int tile = blockIdx.x * 128;
    int cnt = N - tile; if (cnt > 128) cnt = 128;

    // bulk coalesced copy: cnt*16 floats = cnt*4 float4s
    {
        const float4* srcA = reinterpret_cast<const float4*>(g_agg + (size_t)tile * FP);
        float4* dstA = reinterpret_cast<float4*>(sAgg);
        int nq = cnt * 4;
        for (int k = t; k < nq; k += 256) dstA[k] = srcA[k];
    }
    for (int k = t; k < 640; k += 256) sW[k] = g_Weff[k];
    if (t < 64) sb[t] = g_beff[t];
    __syncthreads();

    int lane = t & 31;
    int warp = t >> 5;
    float w0[10], w1[10];
#pragma unroll
    for (int k = 0; k < 10; k++) {
        w0[k] = sW[k * 64 + lane];
        w1[k] = sW[k * 64 + 32 + lane];
    }
    float b0 = sb[lane];
    float b1 = sb[lane + 32];

    for (int i = warp; i < cnt; i += 8) {
        const float4* r = reinterpret_cast<const float4*>(sAgg + i * FP);
        float4 a0 = r[0], a1 = r[1], a2 = r[2];   // LDS broadcast, 29cyc
        float nd = rsqrtf(a2.z > 0.f ? a2.z : 1.f);
        float s0 = a0.x * w0[0] + a0.y * w0[1] + a0.z * w0[2] + a0.w * w0[3]
                 + a1.x * w0[4] + a1.y * w0[5] + a1.z * w0[6] + a1.w * w0[7]
                 + a2.x * w0[8] + a2.y * w0[9];
        float s1 = a0.x * w1[0] + a0.y * w1[1] + a0.z * w1[2] + a0.w * w1[3]
                 + a1.x * w1[4] + a1.y * w1[5] + a1.z * w1[6] + a1.w * w1[7]
                 + a2.x * w1[8] + a2.y * w1[9];
        float* orow = out + (size_t)(tile + i) * 64;
        orow[lane]      = b0 + nd * s0;
        orow[lane + 32] = b1 + nd * s1;
    }
}

// ---------------------------------------------------------------- launch
extern "C" void kernel_launch(void* const* d_in, const int* in_sizes, int n_in,
                              void* d_out, int out_size) {
    const float* x   = (const float*)d_in[0];
    const int*   src = (const int*)d_in[1];
    const int*   dst = (const int*)d_in[2];
    const float* W1  = (const float*)d_in[3];
    const float* b1  = (const float*)d_in[4];
    const float* W2  = (const float*)d_in[5];
    const float* b2  = (const float*)d_in[6];
    float* out = (float*)d_out;

    int N = in_sizes[0] / 40;
    int E = in_sizes[1];

    void* p_agg = nullptr;
    void* p_deg = nullptr;
    cudaGetSymbolAddress(&p_agg, g_agg);
    cudaGetSymbolAddress(&p_deg, g_deg_out);
    cudaMemsetAsync(p_agg, 0, (size_t)N * FP * sizeof(float));
    cudaMemsetAsync(p_deg, 0, (size_t)N * sizeof(int));

    int n8 = E >> 3;
    int db = (n8 > 0 ? (n8 + 255) / 256 : 1) + 1;          // +1 block for weff
    k_deg_weff<<<db, 256>>>(src, E, W1, b1, W2, b2);
    k_prep<<<(N + 255) / 256, 256>>>(x, N);

    long groups = ((long)E + 7) / 8;                        // 4 lanes per group
    long sthreads = groups * 4;
    int sblocks = (int)((sthreads + 255) / 256);
    k_scatter<<<sblocks, 256>>>(src, dst, E);

    k_out<<<(N + 127) / 128, 256>>>(out, N);                // one 128-node tile per block
}

// round 13
// speedup vs baseline: 1.5915x; 1.0488x over previous
#include <cuda_runtime.h>

// GCN_75050258530542 — round 12: R10 scatter (v4 REDs, the fp32 floor),
// 256-node smem-staged k_out, self-cleaning scratch (no memsets: k_out
// re-zeroes g_agg + g_deg_out for the next call; globals start zero-init).
// out[n,:] = rsqrt(deg_in[n]) * (sum_{e:dst=n} x[src,15:25]*rsqrt(deg_out[src])) @ (W1@W2)
//            + (b1@W2 + b2)

constexpr int NMAX = 100000;
constexpr int FP   = 16;   // 64B rows, 128B-aligned: 4-lane group hits 1 line

__device__ int g_deg_out[NMAX];
__device__ __align__(128) float g_xsn[NMAX * FP];   // slots 0-9 = x[:,15:25]*norm_s; pad 0
__device__ __align__(128) float g_agg[NMAX * FP];   // slots 0-9 sums, slot 10 = deg_in
__device__ float g_Weff[640];                       // W1@W2 (10 x 64)
__device__ float g_beff[64];                        // b1@W2 + b2

// ---------------------------------------------------------------- degrees + weff (last block)
__global__ void k_deg_weff(const int* __restrict__ src, int E,
                           const float* __restrict__ W1, const float* __restrict__ b1,
                           const float* __restrict__ W2, const float* __restrict__ b2) {
    int nb = gridDim.x - 1;
    if ((int)blockIdx.x == nb) {
        for (int idx = threadIdx.x; idx < 704; idx += blockDim.x) {
            if (idx < 640) {
                int i = idx >> 6, j = idx & 63;
                float s = 0.f;
#pragma unroll 8
                for (int k = 0; k < 128; k++) s += W1[i * 128 + k] * W2[k * 64 + j];
                g_Weff[idx] = s;
            } else {
                int j = idx - 640;
                float s = b2[j];
#pragma unroll 8
                for (int k = 0; k < 128; k++) s += b1[k] * W2[k * 64 + j];
                g_beff[j] = s;
            }
        }
        return;
    }
    int n8 = E >> 3;
    int stride = nb * blockDim.x;
    for (int t = blockIdx.x * blockDim.x + threadIdx.x; t < n8; t += stride) {
        int4 s0 = reinterpret_cast<const int4*>(src)[2 * t];
        int4 s1 = reinterpret_cast<const int4*>(src)[2 * t + 1];
        atomicAdd(&g_deg_out[s0.x], 1);
        atomicAdd(&g_deg_out[s0.y], 1);
        atomicAdd(&g_deg_out[s0.z], 1);
        atomicAdd(&g_deg_out[s0.w], 1);
        atomicAdd(&g_deg_out[s1.x], 1);
        atomicAdd(&g_deg_out[s1.y], 1);
        atomicAdd(&g_deg_out[s1.z], 1);
        atomicAdd(&g_deg_out[s1.w], 1);
    }
    if (blockIdx.x == 0 && threadIdx.x == 0) {
        for (int e = (n8 << 3); e < E; e++) atomicAdd(&g_deg_out[src[e]], 1);
    }
}

// ---------------------------------------------------------------- prep: xsn = x[:,15:25]*norm_s
__global__ void k_prep(const float* __restrict__ x, int N) {
    int i = blockIdx.x * blockDim.x + threadIdx.x;
    if (i >= N) return;
    int dout = g_deg_out[i];
    float ns = rsqrtf(dout > 0 ? (float)dout : 1.f);
    const float* base = x + (size_t)i * 40;
    float4 L0 = *reinterpret_cast<const float4*>(base + 12);
    float4 L1 = *reinterpret_cast<const float4*>(base + 16);
    float4 L2 = *reinterpret_cast<const float4*>(base + 20);
    float4 L3 = *reinterpret_cast<const float4*>(base + 24);
    float* o = g_xsn + i * FP;
    *reinterpret_cast<float4*>(o)     = make_float4(L0.w * ns, L1.x * ns, L1.y * ns, L1.z * ns); // c15-18
    *reinterpret_cast<float4*>(o + 4) = make_float4(L1.w * ns, L2.x * ns, L2.y * ns, L2.z * ns); // c19-22
    *reinterpret_cast<float4*>(o + 8) = make_float4(L2.w * ns, L3.x * ns, 0.f, 0.f);             // c23-24, pad
}

// ---------------------------------------------------------------- vector RED
__device__ __forceinline__ void red4(float* p, float a, float b, float c, float d) {
    asm volatile("red.global.add.v4.f32 [%0], {%1,%2,%3,%4};"
                 :: "l"(p), "f"(a), "f"(b), "f"(c), "f"(d) : "memory");
}

// ---------------------------------------------------------------- scatter: 4 lanes/edge, 8 edges/group (R10)
__global__ void __launch_bounds__(256) k_scatter(const int* __restrict__ src,
                                                 const int* __restrict__ dst, int E) {
    int tid = blockIdx.x * blockDim.x + threadIdx.x;
    int g = tid >> 2;          // edge group (8 edges)
    int q = tid & 3;           // quarter within feature row
    long base = (long)g * 8;
    if (base >= E) return;

    unsigned am = 0xffffffffu;
    int full = (base + 8 <= (long)E);

    int dd[8];
    float4 v[8];
    if (full) {
        int s2a = __ldg(src + base + 2 * q);
        int s2b = __ldg(src + base + 2 * q + 1);
        int d2a = __ldg(dst + base + 2 * q);
        int d2b = __ldg(dst + base + 2 * q + 1);
        int lq = (tid & 31) & ~3;
#pragma unroll
        for (int j = 0; j < 8; j++) {
            int owner = lq + (j >> 1);
            int sj = __shfl_sync(am, (j & 1) ? s2b : s2a, owner);
            dd[j]  = __shfl_sync(am, (j & 1) ? d2b : d2a, owner);
            if (q < 3) v[j] = *reinterpret_cast<const float4*>(g_xsn + (size_t)sj * FP + q * 4);
        }
#pragma unroll
        for (int j = 0; j < 8; j++) {
            if (q < 3) {
                float4 p = v[j];
                if (q == 2) { p.z = 1.0f; p.w = 0.0f; }   // slot 10 += 1 (deg_in)
                red4(g_agg + (size_t)dd[j] * FP + q * 4, p.x, p.y, p.z, p.w);
            }
        }
    } else {
        int cnt = (int)(E - base);
        for (int j = 0; j < cnt; j++) {
            int sj = __ldg(src + base + j);
            int dj = __ldg(dst + base + j);
            if (q < 3) {
                float4 p = *reinterpret_cast<const float4*>(g_xsn + (size_t)sj * FP + q * 4);
                if (q == 2) { p.z = 1.0f; p.w = 0.0f; }
                red4(g_agg + (size_t)dj * FP + q * 4, p.x, p.y, p.z, p.w);
            }
        }
    }
}

// ---------------------------------------------------------------- k_out: 256-node smem tile + scratch cleanup
__global__ void __launch_bounds__(512) k_out(float* __restrict__ out, int N) {
    __shared__ float sW[640];
    __shared__ float sb[64];
    __shared__ __align__(16) float sAgg[256 * FP];   // 16KB tile
    int t = threadIdx.x;

    int tile = blockIdx.x * 256;
    int cnt = N - tile; if (cnt > 256) cnt = 256;
    int nq = cnt * 4;

    float4* gAgg4 = reinterpret_cast<float4*>(g_agg + (size_t)tile * FP);
    {
        float4* dstA = reinterpret_cast<float4*>(sAgg);
        for (int k = t; k < nq; k += 512) dstA[k] = gAgg4[k];
    }
    for (int k = t; k < 640; k += 512) sW[k] = g_Weff[k];
    if (t < 64) sb[t] = g_beff[t];
    __syncthreads();

    // scratch cleanup for the next kernel_launch call (self-zeroing pipeline):
    // this block owns rows [tile, tile+cnt) exclusively.
    {
        float4 z = {0.f, 0.f, 0.f, 0.f};
        for (int k = t; k < nq; k += 512) gAgg4[k] = z;
        if (t < cnt) g_deg_out[tile + t] = 0;
    }

    int lane = t & 31;
    int warp = t >> 5;          // 16 warps
    float w0[10], w1[10];
#pragma unroll
    for (int k = 0; k < 10; k++) {
        w0[k] = sW[k * 64 + lane];
        w1[k] = sW[k * 64 + 32 + lane];
    }
    float b0 = sb[lane];
    float b1 = sb[lane + 32];

    for (int i = warp; i < cnt; i += 16) {
        const float4* r = reinterpret_cast<const float4*>(sAgg + i * FP);
        float4 a0 = r[0], a1 = r[1], a2 = r[2];   // LDS broadcast
        float nd = rsqrtf(a2.z > 0.f ? a2.z : 1.f);
        float s0 = a0.x * w0[0] + a0.y * w0[1] + a0.z * w0[2] + a0.w * w0[3]
                 + a1.x * w0[4] + a1.y * w0[5] + a1.z * w0[6] + a1.w * w0[7]
                 + a2.x * w0[8] + a2.y * w0[9];
        float s1 = a0.x * w1[0] + a0.y * w1[1] + a0.z * w1[2] + a0.w * w1[3]
                 + a1.x * w1[4] + a1.y * w1[5] + a1.z * w1[6] + a1.w * w1[7]
                 + a2.x * w1[8] + a2.y * w1[9];
        float* orow = out + (size_t)(tile + i) * 64;
        orow[lane]      = b0 + nd * s0;
        orow[lane + 32] = b1 + nd * s1;
    }
}

// ---------------------------------------------------------------- launch
extern "C" void kernel_launch(void* const* d_in, const int* in_sizes, int n_in,
                              void* d_out, int out_size) {
    const float* x   = (const float*)d_in[0];
    const int*   src = (const int*)d_in[1];
    const int*   dst = (const int*)d_in[2];
    const float* W1  = (const float*)d_in[3];
    const float* b1  = (const float*)d_in[4];
    const float* W2  = (const float*)d_in[5];
    const float* b2  = (const float*)d_in[6];
    float* out = (float*)d_out;

    int N = in_sizes[0] / 40;
    int E = in_sizes[1];

    // no memsets: g_agg / g_deg_out start zero (module init) and are re-zeroed
    // at the end of every k_out, so each call sees clean scratch.

    int n8 = E >> 3;
    int db = (n8 > 0 ? (n8 + 255) / 256 : 1) + 1;          // +1 block for weff
    k_deg_weff<<<db, 256>>>(src, E, W1, b1, W2, b2);
    k_prep<<<(N + 255) / 256, 256>>>(x, N);

    long groups = ((long)E + 7) / 8;                        // 4 lanes per group
    long sthreads = groups * 4;
    int sblocks = (int)((sthreads + 255) / 256);
    k_scatter<<<sblocks, 256>>>(src, dst, E);

    k_out<<<(N + 255) / 256, 512>>>(out, N);                // 256-node tiles + cleanup
}